// round 1
// baseline (speedup 1.0000x reference)
#include <cuda_runtime.h>

// ProtoSupConLoss on sm_100a.
// B=8, S=2048, D=128, C=64. Dominant cost: per-batch SxS Gram (K=D=128) with
// fused exp + row reductions (row_sum, same-label sum, E[i, rank_i]).
// Centroid term fused into the same block after the j-loop.

namespace {
constexpr int Bn = 8, Sn = 2048, Dn = 128, Cn = 64;
constexpr float DIMNORM = 11.313708498984761f;            // sqrt(128)
constexpr float INV_T   = 1.0f / (0.7f * 11.313708498984761f);
constexpr int TM  = 128;     // i/j tile
constexpr int LDT = 132;     // padded smem tile stride (floats)
constexpr int NTHREADS = 512;
}

__device__ float  g_sq[Bn * Sn];
__device__ float  g_csq[Cn];
__device__ float  g_iphi[Cn];
__device__ int    g_lab[Bn * Sn];
__device__ int    g_rank[Bn * Sn];
__device__ int    g_cnt[Bn * Sn];
__device__ double g_loss;

struct Smem {
    float As[Dn * LDT];      // A tile transposed: As[k*LDT + row]
    float Bs[Dn * LDT];      // B tile transposed: Bs[k*LDT + col]
    float Cs[Dn * Cn];       // centroids transposed: Cs[k*Cn + c]
    float sqj[TM];
    int   labj[TM];
    float csq[Cn];
    float iphi[Cn];
    float row_rs[TM];
    float row_pos[TM];
    float row_er[TM];
    double loss;
};

// ---------------------------------------------------------------------------
// Kernel 0: normalize labels (int64-vs-int32 autodetect) + zero accumulator.
// Safe: reads only the first Bn*Sn 32-bit words for detection (valid for both
// dtypes). Labels are in [0,64), so for int64 every odd word is 0; for int32
// the odd words are labels at odd indices (P(all zero) ~ 0).
// ---------------------------------------------------------------------------
__global__ void label_kernel(const int* __restrict__ lab32) {
    __shared__ int nz;
    if (threadIdx.x == 0) nz = 0;
    __syncthreads();
    int local = 0;
    for (int w = 1 + 2 * (int)threadIdx.x; w < Bn * Sn; w += 2 * (int)blockDim.x)
        local |= lab32[w];
    if (local) atomicOr(&nz, 1);
    __syncthreads();
    const bool is64 = (nz == 0);
    for (int i = threadIdx.x; i < Bn * Sn; i += blockDim.x)
        g_lab[i] = is64 ? lab32[2 * i] : lab32[i];
    if (threadIdx.x == 0) g_loss = 0.0;
}

// ---------------------------------------------------------------------------
// Kernel 1: per-row sq, per-row rank/count (within batch), centroid sq, 1/phi.
// One block per batch, 1024 threads.
// ---------------------------------------------------------------------------
__global__ void __launch_bounds__(1024) prep_kernel(
    const float* __restrict__ feat,
    const float* __restrict__ cent,
    const float* __restrict__ phi)
{
    const int b = blockIdx.x;
    const int tid = threadIdx.x;
    __shared__ int labs[Sn];

    for (int i = tid; i < Sn; i += 1024) labs[i] = g_lab[b * Sn + i];
    __syncthreads();

    // rank = #earlier same-label, cnt = #same-label total (incl. self).
    for (int r = tid; r < Sn; r += 1024) {
        const int l = labs[r];
        int rk = 0, cnt = 0;
        for (int j = 0; j < Sn; ++j) {            // uniform loop -> LDS broadcast
            const int e = (labs[j] == l);
            cnt += e;
            rk  += (j < r) ? e : 0;
        }
        g_rank[b * Sn + r] = rk;
        g_cnt[b * Sn + r]  = cnt;
    }

    // per-row squared norms (one warp per row, float4 lanes)
    const int wid = tid >> 5, lane = tid & 31;
    for (int r = wid; r < Sn; r += 32) {
        const float4 v = reinterpret_cast<const float4*>(
            feat + ((size_t)b * Sn + r) * Dn)[lane];
        float s = v.x * v.x + v.y * v.y + v.z * v.z + v.w * v.w;
        #pragma unroll
        for (int o = 16; o; o >>= 1) s += __shfl_xor_sync(0xffffffffu, s, o);
        if (lane == 0) g_sq[b * Sn + r] = s;
    }

    if (b == 0) {
        for (int c = wid; c < Cn; c += 32) {
            const float4 v = reinterpret_cast<const float4*>(cent + (size_t)c * Dn)[lane];
            float s = v.x * v.x + v.y * v.y + v.z * v.z + v.w * v.w;
            #pragma unroll
            for (int o = 16; o; o >>= 1) s += __shfl_xor_sync(0xffffffffu, s, o);
            if (lane == 0) g_csq[c] = s;
        }
        if (tid < Cn) g_iphi[tid] = 1.0f / (phi[tid] * DIMNORM);
    }
}

// ---------------------------------------------------------------------------
// Kernel 2: main fused Gram+exp+reduce + centroid term + per-row loss term.
// Grid: (S/TM, B). 512 threads, each owns a 4x8 microtile of the 128x128 tile.
// ---------------------------------------------------------------------------
__global__ void __launch_bounds__(NTHREADS, 1) main_kernel(
    const float* __restrict__ feat,
    const float* __restrict__ cent)
{
    extern __shared__ unsigned char smem_raw[];
    Smem& sm = *reinterpret_cast<Smem*>(smem_raw);

    const int tid   = threadIdx.x;
    const int b     = blockIdx.y;
    const int iBase = blockIdx.x * TM;
    const int tx    = tid & 15;    // 0..15  -> columns
    const int ty    = tid >> 4;    // 0..31  -> rows
    const float* Fb = feat + (size_t)b * Sn * Dn;

    // Load A tile transposed (As[k][row]).
    for (int t = tid; t < TM * 32; t += NTHREADS) {
        const int r = t >> 5, d4 = (t & 31) << 2;
        const float4 v = *reinterpret_cast<const float4*>(
            Fb + (size_t)(iBase + r) * Dn + d4);
        sm.As[(d4 + 0) * LDT + r] = v.x;
        sm.As[(d4 + 1) * LDT + r] = v.y;
        sm.As[(d4 + 2) * LDT + r] = v.z;
        sm.As[(d4 + 3) * LDT + r] = v.w;
    }
    // Centroids transposed (Cs[k][c]).
    for (int t = tid; t < Cn * 32; t += NTHREADS) {
        const int c = t >> 5, d4 = (t & 31) << 2;
        const float4 v = *reinterpret_cast<const float4*>(cent + (size_t)c * Dn + d4);
        sm.Cs[(d4 + 0) * Cn + c] = v.x;
        sm.Cs[(d4 + 1) * Cn + c] = v.y;
        sm.Cs[(d4 + 2) * Cn + c] = v.z;
        sm.Cs[(d4 + 3) * Cn + c] = v.w;
    }
    if (tid < Cn) { sm.csq[tid] = g_csq[tid]; sm.iphi[tid] = g_iphi[tid]; }
    if (tid == 0) sm.loss = 0.0;

    // Per-thread row context (4 rows: ty*4 + m).
    int   rowl[4]; float sqi[4]; int labi[4], ranki[4];
    #pragma unroll
    for (int m = 0; m < 4; ++m) {
        const int r = ty * 4 + m;
        rowl[m] = r;
        const int gi = b * Sn + iBase + r;
        sqi[m]   = g_sq[gi];
        labi[m]  = g_lab[gi];
        ranki[m] = g_rank[gi];
    }

    float rs[4] = {0, 0, 0, 0};   // row_sum partials
    float ps[4] = {0, 0, 0, 0};   // same-label (excl self) partials
    float er[4] = {0, 0, 0, 0};   // E[i, rank_i] (exactly one hit per row)

    for (int jt = 0; jt < Sn / TM; ++jt) {
        const int jBase = jt * TM;
        __syncthreads();    // protect Bs/sqj/labj from previous epilogue
        for (int t = tid; t < TM * 32; t += NTHREADS) {
            const int r = t >> 5, d4 = (t & 31) << 2;
            const float4 v = *reinterpret_cast<const float4*>(
                Fb + (size_t)(jBase + r) * Dn + d4);
            sm.Bs[(d4 + 0) * LDT + r] = v.x;
            sm.Bs[(d4 + 1) * LDT + r] = v.y;
            sm.Bs[(d4 + 2) * LDT + r] = v.z;
            sm.Bs[(d4 + 3) * LDT + r] = v.w;
        }
        if (tid < TM) {
            const int gj = b * Sn + jBase + tid;
            sm.sqj[tid]  = g_sq[gj];
            sm.labj[tid] = g_lab[gj];
        }
        __syncthreads();

        float acc[4][8];
        #pragma unroll
        for (int m = 0; m < 4; ++m)
            #pragma unroll
            for (int n = 0; n < 8; ++n) acc[m][n] = 0.f;

        #pragma unroll 4
        for (int k = 0; k < Dn; ++k) {
            const float4 av = *reinterpret_cast<const float4*>(&sm.As[k * LDT + ty * 4]);
            const float4 b0 = *reinterpret_cast<const float4*>(&sm.Bs[k * LDT + tx * 4]);
            const float4 b1 = *reinterpret_cast<const float4*>(&sm.Bs[k * LDT + 64 + tx * 4]);
            const float a[4]  = {av.x, av.y, av.z, av.w};
            const float bb[8] = {b0.x, b0.y, b0.z, b0.w, b1.x, b1.y, b1.z, b1.w};
            #pragma unroll
            for (int m = 0; m < 4; ++m)
                #pragma unroll
                for (int n = 0; n < 8; ++n)
                    acc[m][n] = fmaf(a[m], bb[n], acc[m][n]);
        }

        // Fused epilogue: exp + masked row accumulation.
        float sqjn[8]; int labjn[8], coln[8];
        #pragma unroll
        for (int n = 0; n < 8; ++n) {
            const int cidx = (n < 4) ? (tx * 4 + n) : (64 + tx * 4 + (n - 4));
            coln[n]  = jBase + cidx;
            sqjn[n]  = sm.sqj[cidx];
            labjn[n] = sm.labj[cidx];
        }
        #pragma unroll
        for (int m = 0; m < 4; ++m) {
            const int ig = iBase + rowl[m];
            #pragma unroll
            for (int n = 0; n < 8; ++n) {
                const float d2 = sqi[m] + sqjn[n] - 2.0f * acc[m][n];
                const float e  = __expf(d2 * INV_T);
                rs[m] += e;
                if (labjn[n] == labi[m] && coln[n] != ig) ps[m] += e;
                if (coln[n] == ranki[m]) er[m] += e;
            }
        }
    }

    // Reduce across the 16 column-threads (contiguous half-warp, same ty).
    #pragma unroll
    for (int m = 0; m < 4; ++m) {
        #pragma unroll
        for (int o = 1; o < 16; o <<= 1) {
            rs[m] += __shfl_xor_sync(0xffffffffu, rs[m], o);
            ps[m] += __shfl_xor_sync(0xffffffffu, ps[m], o);
            er[m] += __shfl_xor_sync(0xffffffffu, er[m], o);
        }
    }
    if (tx == 0) {
        #pragma unroll
        for (int m = 0; m < 4; ++m) {
            sm.row_rs[rowl[m]]  = rs[m];
            sm.row_pos[rowl[m]] = ps[m];
            sm.row_er[rowl[m]]  = er[m];
        }
    }
    __syncthreads();

    // Centroid phase: thread -> (row = tid>>2, 16-wide c chunk).
    const int r  = tid >> 2;
    const int ch = (tid & 3) << 4;
    float cacc[16];
    #pragma unroll
    for (int cc = 0; cc < 16; ++cc) cacc[cc] = 0.f;
    #pragma unroll 4
    for (int k = 0; k < Dn; ++k) {
        const float fv = sm.As[k * LDT + r];
        #pragma unroll
        for (int cc = 0; cc < 16; ++cc)
            cacc[cc] = fmaf(fv, sm.Cs[k * Cn + ch + cc], cacc[cc]);
    }
    const int gi     = b * Sn + iBase + r;
    const float sq_r = g_sq[gi];
    const int lab_r  = g_lab[gi];
    float sum_ce = 0.f, ce_lab = 0.f;
    #pragma unroll
    for (int cc = 0; cc < 16; ++cc) {
        const int cIdx = ch + cc;
        const float cd2 = sq_r + sm.csq[cIdx] - 2.0f * cacc[cc];
        const float ce  = __expf(cd2 * sm.iphi[cIdx]);
        sum_ce += ce;
        if (cIdx == lab_r) ce_lab = ce;
    }
    #pragma unroll
    for (int o = 1; o < 4; o <<= 1) {
        sum_ce += __shfl_xor_sync(0xffffffffu, sum_ce, o);
        ce_lab += __shfl_xor_sync(0xffffffffu, ce_lab, o);
    }

    float term = 0.f;
    if ((tid & 3) == 0) {
        const float pos_spcl = sm.row_pos[r] + ce_lab;
        const float neg_spcl = (sm.row_rs[r] - sm.row_er[r]) + (sum_ce - ce_lab);
        const float denom    = (float)(g_cnt[gi] + 1);
        term = logf(denom * neg_spcl) - logf(pos_spcl);
    }
    #pragma unroll
    for (int o = 16; o > 0; o >>= 1) term += __shfl_xor_sync(0xffffffffu, term, o);
    if ((tid & 31) == 0) atomicAdd(&sm.loss, (double)term);
    __syncthreads();
    if (tid == 0) atomicAdd(&g_loss, sm.loss);
}

__global__ void finish_kernel(float* __restrict__ out) {
    out[0] = (float)(g_loss * (1.0 / (double)Sn));
}

// ---------------------------------------------------------------------------
extern "C" void kernel_launch(void* const* d_in, const int* in_sizes, int n_in,
                              void* d_out, int out_size) {
    (void)in_sizes; (void)n_in; (void)out_size;
    const float* feat   = (const float*)d_in[0];
    const int*   lab32  = (const int*)d_in[1];   // int32 or int64 (autodetected)
    const float* cent   = (const float*)d_in[2];
    const float* phi    = (const float*)d_in[3];
    float* out = (float*)d_out;

    cudaFuncSetAttribute(main_kernel, cudaFuncAttributeMaxDynamicSharedMemorySize,
                         (int)sizeof(Smem));

    label_kernel<<<1, 1024>>>(lab32);
    prep_kernel<<<Bn, 1024>>>(feat, cent, phi);
    main_kernel<<<dim3(Sn / TM, Bn), NTHREADS, sizeof(Smem)>>>(feat, cent);
    finish_kernel<<<1, 1>>>(out);
}

// round 2
// speedup vs baseline: 1.0008x; 1.0008x over previous
#include <cuda_runtime.h>

// ProtoSupConLoss on sm_100a.
// B=8, S=2048, D=128, C=64. Dominant cost: per-batch SxS Gram (K=D=128) with
// fused exp + row reductions (row_sum, same-label sum, E[i, rank_i]).
// Centroid term fused into the same block after the j-loop.

namespace {
constexpr int Bn = 8, Sn = 2048, Dn = 128, Cn = 64;
constexpr float DIMNORM = 11.313708498984761f;            // sqrt(128)
constexpr float INV_T   = 1.0f / (0.7f * 11.313708498984761f);
constexpr int TM  = 128;     // i/j tile
constexpr int LDT = 132;     // padded smem tile stride (floats)
constexpr int NTHREADS = 512;
}

__device__ float  g_sq[Bn * Sn];
__device__ float  g_csq[Cn];
__device__ float  g_iphi[Cn];
__device__ int    g_lab[Bn * Sn];
__device__ int    g_rank[Bn * Sn];
__device__ int    g_cnt[Bn * Sn];
__device__ double g_loss;

struct Smem {
    float As[Dn * LDT];      // A tile transposed: As[k*LDT + row]
    float Bs[Dn * LDT];      // B tile transposed: Bs[k*LDT + col]
    float Cs[Dn * Cn];       // centroids transposed: Cs[k*Cn + c]
    float sqj[TM];
    int   labj[TM];
    float csq[Cn];
    float iphi[Cn];
    float row_rs[TM];
    float row_pos[TM];
    float row_er[TM];
    double loss;
};

// ---------------------------------------------------------------------------
// Kernel 0: normalize labels (int64-vs-int32 autodetect) + zero accumulator.
// Safe: reads only the first Bn*Sn 32-bit words for detection (valid for both
// dtypes). Labels are in [0,64), so for int64 every odd word is 0; for int32
// the odd words are labels at odd indices (P(all zero) ~ 0).
// ---------------------------------------------------------------------------
__global__ void label_kernel(const int* __restrict__ lab32) {
    __shared__ int nz;
    if (threadIdx.x == 0) nz = 0;
    __syncthreads();
    int local = 0;
    for (int w = 1 + 2 * (int)threadIdx.x; w < Bn * Sn; w += 2 * (int)blockDim.x)
        local |= lab32[w];
    if (local) atomicOr(&nz, 1);
    __syncthreads();
    const bool is64 = (nz == 0);
    for (int i = threadIdx.x; i < Bn * Sn; i += blockDim.x)
        g_lab[i] = is64 ? lab32[2 * i] : lab32[i];
    if (threadIdx.x == 0) g_loss = 0.0;
}

// ---------------------------------------------------------------------------
// Kernel 1: per-row sq, per-row rank/count (within batch), centroid sq, 1/phi.
// One block per batch, 1024 threads.
// ---------------------------------------------------------------------------
__global__ void __launch_bounds__(1024) prep_kernel(
    const float* __restrict__ feat,
    const float* __restrict__ cent,
    const float* __restrict__ phi)
{
    const int b = blockIdx.x;
    const int tid = threadIdx.x;
    __shared__ int labs[Sn];

    for (int i = tid; i < Sn; i += 1024) labs[i] = g_lab[b * Sn + i];
    __syncthreads();

    // rank = #earlier same-label, cnt = #same-label total (incl. self).
    for (int r = tid; r < Sn; r += 1024) {
        const int l = labs[r];
        int rk = 0, cnt = 0;
        for (int j = 0; j < Sn; ++j) {            // uniform loop -> LDS broadcast
            const int e = (labs[j] == l);
            cnt += e;
            rk  += (j < r) ? e : 0;
        }
        g_rank[b * Sn + r] = rk;
        g_cnt[b * Sn + r]  = cnt;
    }

    // per-row squared norms (one warp per row, float4 lanes)
    const int wid = tid >> 5, lane = tid & 31;
    for (int r = wid; r < Sn; r += 32) {
        const float4 v = reinterpret_cast<const float4*>(
            feat + ((size_t)b * Sn + r) * Dn)[lane];
        float s = v.x * v.x + v.y * v.y + v.z * v.z + v.w * v.w;
        #pragma unroll
        for (int o = 16; o; o >>= 1) s += __shfl_xor_sync(0xffffffffu, s, o);
        if (lane == 0) g_sq[b * Sn + r] = s;
    }

    if (b == 0) {
        for (int c = wid; c < Cn; c += 32) {
            const float4 v = reinterpret_cast<const float4*>(cent + (size_t)c * Dn)[lane];
            float s = v.x * v.x + v.y * v.y + v.z * v.z + v.w * v.w;
            #pragma unroll
            for (int o = 16; o; o >>= 1) s += __shfl_xor_sync(0xffffffffu, s, o);
            if (lane == 0) g_csq[c] = s;
        }
        if (tid < Cn) g_iphi[tid] = 1.0f / (phi[tid] * DIMNORM);
    }
}

// ---------------------------------------------------------------------------
// Kernel 2: main fused Gram+exp+reduce + centroid term + per-row loss term.
// Grid: (S/TM, B). 512 threads, each owns a 4x8 microtile of the 128x128 tile.
// ---------------------------------------------------------------------------
__global__ void __launch_bounds__(NTHREADS, 1) main_kernel(
    const float* __restrict__ feat,
    const float* __restrict__ cent)
{
    extern __shared__ unsigned char smem_raw[];
    Smem& sm = *reinterpret_cast<Smem*>(smem_raw);

    const int tid   = threadIdx.x;
    const int b     = blockIdx.y;
    const int iBase = blockIdx.x * TM;
    const int tx    = tid & 15;    // 0..15  -> columns
    const int ty    = tid >> 4;    // 0..31  -> rows
    const float* Fb = feat + (size_t)b * Sn * Dn;

    // Load A tile transposed (As[k][row]).
    for (int t = tid; t < TM * 32; t += NTHREADS) {
        const int r = t >> 5, d4 = (t & 31) << 2;
        const float4 v = *reinterpret_cast<const float4*>(
            Fb + (size_t)(iBase + r) * Dn + d4);
        sm.As[(d4 + 0) * LDT + r] = v.x;
        sm.As[(d4 + 1) * LDT + r] = v.y;
        sm.As[(d4 + 2) * LDT + r] = v.z;
        sm.As[(d4 + 3) * LDT + r] = v.w;
    }
    // Centroids transposed (Cs[k][c]).
    for (int t = tid; t < Cn * 32; t += NTHREADS) {
        const int c = t >> 5, d4 = (t & 31) << 2;
        const float4 v = *reinterpret_cast<const float4*>(cent + (size_t)c * Dn + d4);
        sm.Cs[(d4 + 0) * Cn + c] = v.x;
        sm.Cs[(d4 + 1) * Cn + c] = v.y;
        sm.Cs[(d4 + 2) * Cn + c] = v.z;
        sm.Cs[(d4 + 3) * Cn + c] = v.w;
    }
    if (tid < Cn) { sm.csq[tid] = g_csq[tid]; sm.iphi[tid] = g_iphi[tid]; }
    if (tid == 0) sm.loss = 0.0;

    // Per-thread row context (4 rows: ty*4 + m).
    int   rowl[4]; float sqi[4]; int labi[4], ranki[4];
    #pragma unroll
    for (int m = 0; m < 4; ++m) {
        const int r = ty * 4 + m;
        rowl[m] = r;
        const int gi = b * Sn + iBase + r;
        sqi[m]   = g_sq[gi];
        labi[m]  = g_lab[gi];
        ranki[m] = g_rank[gi];
    }

    float rs[4] = {0, 0, 0, 0};   // row_sum partials
    float ps[4] = {0, 0, 0, 0};   // same-label (excl self) partials
    float er[4] = {0, 0, 0, 0};   // E[i, rank_i] (exactly one hit per row)

    for (int jt = 0; jt < Sn / TM; ++jt) {
        const int jBase = jt * TM;
        __syncthreads();    // protect Bs/sqj/labj from previous epilogue
        for (int t = tid; t < TM * 32; t += NTHREADS) {
            const int r = t >> 5, d4 = (t & 31) << 2;
            const float4 v = *reinterpret_cast<const float4*>(
                Fb + (size_t)(jBase + r) * Dn + d4);
            sm.Bs[(d4 + 0) * LDT + r] = v.x;
            sm.Bs[(d4 + 1) * LDT + r] = v.y;
            sm.Bs[(d4 + 2) * LDT + r] = v.z;
            sm.Bs[(d4 + 3) * LDT + r] = v.w;
        }
        if (tid < TM) {
            const int gj = b * Sn + jBase + tid;
            sm.sqj[tid]  = g_sq[gj];
            sm.labj[tid] = g_lab[gj];
        }
        __syncthreads();

        float acc[4][8];
        #pragma unroll
        for (int m = 0; m < 4; ++m)
            #pragma unroll
            for (int n = 0; n < 8; ++n) acc[m][n] = 0.f;

        #pragma unroll 4
        for (int k = 0; k < Dn; ++k) {
            const float4 av = *reinterpret_cast<const float4*>(&sm.As[k * LDT + ty * 4]);
            const float4 b0 = *reinterpret_cast<const float4*>(&sm.Bs[k * LDT + tx * 4]);
            const float4 b1 = *reinterpret_cast<const float4*>(&sm.Bs[k * LDT + 64 + tx * 4]);
            const float a[4]  = {av.x, av.y, av.z, av.w};
            const float bb[8] = {b0.x, b0.y, b0.z, b0.w, b1.x, b1.y, b1.z, b1.w};
            #pragma unroll
            for (int m = 0; m < 4; ++m)
                #pragma unroll
                for (int n = 0; n < 8; ++n)
                    acc[m][n] = fmaf(a[m], bb[n], acc[m][n]);
        }

        // Fused epilogue: exp + masked row accumulation.
        float sqjn[8]; int labjn[8], coln[8];
        #pragma unroll
        for (int n = 0; n < 8; ++n) {
            const int cidx = (n < 4) ? (tx * 4 + n) : (64 + tx * 4 + (n - 4));
            coln[n]  = jBase + cidx;
            sqjn[n]  = sm.sqj[cidx];
            labjn[n] = sm.labj[cidx];
        }
        #pragma unroll
        for (int m = 0; m < 4; ++m) {
            const int ig = iBase + rowl[m];
            #pragma unroll
            for (int n = 0; n < 8; ++n) {
                const float d2 = sqi[m] + sqjn[n] - 2.0f * acc[m][n];
                const float e  = __expf(d2 * INV_T);
                rs[m] += e;
                if (labjn[n] == labi[m] && coln[n] != ig) ps[m] += e;
                if (coln[n] == ranki[m]) er[m] += e;
            }
        }
    }

    // Reduce across the 16 column-threads (contiguous half-warp, same ty).
    #pragma unroll
    for (int m = 0; m < 4; ++m) {
        #pragma unroll
        for (int o = 1; o < 16; o <<= 1) {
            rs[m] += __shfl_xor_sync(0xffffffffu, rs[m], o);
            ps[m] += __shfl_xor_sync(0xffffffffu, ps[m], o);
            er[m] += __shfl_xor_sync(0xffffffffu, er[m], o);
        }
    }
    if (tx == 0) {
        #pragma unroll
        for (int m = 0; m < 4; ++m) {
            sm.row_rs[rowl[m]]  = rs[m];
            sm.row_pos[rowl[m]] = ps[m];
            sm.row_er[rowl[m]]  = er[m];
        }
    }
    __syncthreads();

    // Centroid phase: thread -> (row = tid>>2, 16-wide c chunk).
    const int r  = tid >> 2;
    const int ch = (tid & 3) << 4;
    float cacc[16];
    #pragma unroll
    for (int cc = 0; cc < 16; ++cc) cacc[cc] = 0.f;
    #pragma unroll 4
    for (int k = 0; k < Dn; ++k) {
        const float fv = sm.As[k * LDT + r];
        #pragma unroll
        for (int cc = 0; cc < 16; ++cc)
            cacc[cc] = fmaf(fv, sm.Cs[k * Cn + ch + cc], cacc[cc]);
    }
    const int gi     = b * Sn + iBase + r;
    const float sq_r = g_sq[gi];
    const int lab_r  = g_lab[gi];
    float sum_ce = 0.f, ce_lab = 0.f;
    #pragma unroll
    for (int cc = 0; cc < 16; ++cc) {
        const int cIdx = ch + cc;
        const float cd2 = sq_r + sm.csq[cIdx] - 2.0f * cacc[cc];
        const float ce  = __expf(cd2 * sm.iphi[cIdx]);
        sum_ce += ce;
        if (cIdx == lab_r) ce_lab = ce;
    }
    #pragma unroll
    for (int o = 1; o < 4; o <<= 1) {
        sum_ce += __shfl_xor_sync(0xffffffffu, sum_ce, o);
        ce_lab += __shfl_xor_sync(0xffffffffu, ce_lab, o);
    }

    float term = 0.f;
    if ((tid & 3) == 0) {
        const float pos_spcl = sm.row_pos[r] + ce_lab;
        const float neg_spcl = (sm.row_rs[r] - sm.row_er[r]) + (sum_ce - ce_lab);
        const float denom    = (float)(g_cnt[gi] + 1);
        term = logf(denom * neg_spcl) - logf(pos_spcl);
    }
    #pragma unroll
    for (int o = 16; o > 0; o >>= 1) term += __shfl_xor_sync(0xffffffffu, term, o);
    if ((tid & 31) == 0) atomicAdd(&sm.loss, (double)term);
    __syncthreads();
    if (tid == 0) atomicAdd(&g_loss, sm.loss);
}

__global__ void finish_kernel(float* __restrict__ out) {
    out[0] = (float)(g_loss * (1.0 / (double)Sn));
}

// ---------------------------------------------------------------------------
extern "C" void kernel_launch(void* const* d_in, const int* in_sizes, int n_in,
                              void* d_out, int out_size) {
    (void)in_sizes; (void)n_in; (void)out_size;
    const float* feat   = (const float*)d_in[0];
    const int*   lab32  = (const int*)d_in[1];   // int32 or int64 (autodetected)
    const float* cent   = (const float*)d_in[2];
    const float* phi    = (const float*)d_in[3];
    float* out = (float*)d_out;

    cudaFuncSetAttribute(main_kernel, cudaFuncAttributeMaxDynamicSharedMemorySize,
                         (int)sizeof(Smem));

    label_kernel<<<1, 1024>>>(lab32);
    prep_kernel<<<Bn, 1024>>>(feat, cent, phi);
    main_kernel<<<dim3(Sn / TM, Bn), NTHREADS, sizeof(Smem)>>>(feat, cent);
    finish_kernel<<<1, 1>>>(out);
}